// round 3
// baseline (speedup 1.0000x reference)
#include <cuda_runtime.h>
#include <cuda_bf16.h>
#include <math.h>
#include <stdint.h>

#define S_     56
#define B_     32
#define C_     1024
#define T_     48
#define H_     1024
#define EMB_   512
#define RANK_  128
#define VOCAB_ 32000
#define TM1    47
#define NROWS  (TM1*B_)     /* 1504 */
#define NRPAD  1536
#define G4     (4*H_)       /* 4096 */
#define K0_    2560         /* EMB + C + H */
#define K1_    2048         /* 2H */

// ---------------- scratch (device globals) ----------------------------------
__device__ __align__(16) __nv_bfloat16 g_W0b[K0_*G4];     // reordered: col=4u+g
__device__ __align__(16) __nv_bfloat16 g_W1b[K1_*G4];     // reordered
__device__ __align__(16) __nv_bfloat16 g_Eb[VOCAB_*RANK_];
__device__ __align__(16) __nv_bfloat16 g_WoB[2048*EMB_];
__device__ __align__(16) __nv_bfloat16 g_embB[TM1*B_*EMB_];
__device__ __align__(16) __nv_bfloat16 g_xa[2][B_*K0_];   // ping-pong [emb|ctx|h0]
__device__ __align__(16) __nv_bfloat16 g_xb[2][B_*K1_];   // ping-pong [h0|h1]
__device__ __align__(16) __nv_bfloat16 g_featsB[NRPAD*2048];  // [h1|ctx] bf16
__device__ __align__(16) __nv_bfloat16 g_tmpB[NRPAD*RANK_];
__device__ float g_c0[B_*H_], g_c1[B_*H_];
__device__ float g_h1[B_*H_];
__device__ float g_hproj[NROWS*EMB_];
__device__ float g_tmp[NROWS*RANK_];
__device__ float g_sumexp[NRPAD];
__device__ float g_lbl[NROWS];

// ---------------- helpers ------------------------------------------------
__device__ __forceinline__ void ldsm_x4(uint32_t* r, const void* p) {
    uint32_t a = (uint32_t)__cvta_generic_to_shared(p);
    asm volatile("ldmatrix.sync.aligned.m8n8.x4.shared.b16 {%0,%1,%2,%3}, [%4];"
        : "=r"(r[0]), "=r"(r[1]), "=r"(r[2]), "=r"(r[3]) : "r"(a));
}
__device__ __forceinline__ void ldsm_x4_t(uint32_t* r, const void* p) {
    uint32_t a = (uint32_t)__cvta_generic_to_shared(p);
    asm volatile("ldmatrix.sync.aligned.m8n8.x4.trans.shared.b16 {%0,%1,%2,%3}, [%4];"
        : "=r"(r[0]), "=r"(r[1]), "=r"(r[2]), "=r"(r[3]) : "r"(a));
}
__device__ __forceinline__ void mma_bf16(float* d, const uint32_t* a, uint32_t b0, uint32_t b1) {
    asm volatile("mma.sync.aligned.m16n8k16.row.col.f32.bf16.bf16.f32 "
        "{%0,%1,%2,%3},{%4,%5,%6,%7},{%8,%9},{%0,%1,%2,%3};"
        : "+f"(d[0]), "+f"(d[1]), "+f"(d[2]), "+f"(d[3])
        : "r"(a[0]), "r"(a[1]), "r"(a[2]), "r"(a[3]), "r"(b0), "r"(b1));
}
__device__ __forceinline__ void cp16(void* s, const void* g) {
    uint32_t sa = (uint32_t)__cvta_generic_to_shared(s);
    asm volatile("cp.async.cg.shared.global [%0], [%1], 16;" :: "r"(sa), "l"(g));
}
__device__ __forceinline__ void cp_commit() { asm volatile("cp.async.commit_group;"); }
__device__ __forceinline__ void cp_wait1()  { asm volatile("cp.async.wait_group 1;"); }

__device__ __forceinline__ float sig_(float x) { return 1.f/(1.f + __expf(-x)); }

// fast exp via 2^y split; FMA-pipe, ~1e-8 rel err, valid |x| < 85
__device__ __forceinline__ float fexp(float x) {
    float y = x * 1.44269504088896341f;
    y = fminf(fmaxf(y, -120.f), 120.f);
    float n = rintf(y);
    float f = y - n;
    float p = 1.53386992e-4f;
    p = fmaf(p, f, 1.33938367e-3f);
    p = fmaf(p, f, 9.61843445e-3f);
    p = fmaf(p, f, 5.55041086e-2f);
    p = fmaf(p, f, 2.40226507e-1f);
    p = fmaf(p, f, 6.93147181e-1f);
    p = fmaf(p, f, 1.0f);
    int e = (int)n;
    return p * __int_as_float((e + 127) << 23);
}

// ---------------- weight reorder + convert ------------------------------------
// gates reordered: new col c = 4*unit + gate ; src col = gate*1024 + unit
__global__ void reorder_w(const float* __restrict__ W0, const float* __restrict__ U0,
                          const float* __restrict__ W1, const float* __restrict__ U1) {
    int idx = blockIdx.x*256 + threadIdx.x;
    const int tot0 = K0_*1024;
    const int tot1 = K1_*1024;
    const float* src; __nv_bfloat16* d;
    int u;
    if (idx < tot0) {
        int k = idx >> 10; u = idx & 1023;
        src = (k < 1536) ? (W0 + (size_t)k*G4) : (U0 + (size_t)(k-1536)*G4);
        d = g_W0b + (size_t)k*G4 + u*4;
    } else if (idx < tot0 + tot1) {
        int j = idx - tot0;
        int k = j >> 10; u = j & 1023;
        src = (k < 1024) ? (W1 + (size_t)k*G4) : (U1 + (size_t)(k-1024)*G4);
        d = g_W1b + (size_t)k*G4 + u*4;
    } else return;
    __nv_bfloat162 p0(__float2bfloat16_rn(src[u]),        __float2bfloat16_rn(src[1024+u]));
    __nv_bfloat162 p1(__float2bfloat16_rn(src[2048+u]),   __float2bfloat16_rn(src[3072+u]));
    *(__nv_bfloat162*)(d)   = p0;
    *(__nv_bfloat162*)(d+2) = p1;
}

#define EE   (VOCAB_*RANK_)
#define WOE  (2048*EMB_)
__global__ void convert_lin(const float* __restrict__ E, const float* __restrict__ Wo) {
    long long i4 = ((long long)blockIdx.x*256 + threadIdx.x) * 4;
    const float* src; __nv_bfloat16* dst;
    if (i4 < EE)            { src = E + i4;        dst = g_Eb  + i4; }
    else if (i4 < EE + WOE) { src = Wo + (i4-EE);  dst = g_WoB + (i4-EE); }
    else return;
    float4 v = *(const float4*)src;
    __nv_bfloat162* d2 = (__nv_bfloat162*)dst;
    d2[0] = __nv_bfloat162(__float2bfloat16_rn(v.x), __float2bfloat16_rn(v.y));
    d2[1] = __nv_bfloat162(__float2bfloat16_rn(v.z), __float2bfloat16_rn(v.w));
}

// ---------------- embedding ----------------------------------------------------
__global__ void embed_kernel(const float* __restrict__ E, const float* __restrict__ P,
                             const int* __restrict__ tok) {
    int t = blockIdx.x / B_;
    int b = blockIdx.x % B_;
    __shared__ float er[RANK_];
    int tid = threadIdx.x;                     // 128
    int token = tok[b*T_ + t];
    er[tid] = E[(size_t)token*RANK_ + tid];
    __syncthreads();
    float acc[4] = {0.f,0.f,0.f,0.f};
    for (int r = 0; r < RANK_; r++) {
        float a = er[r];
        const float* Pr = P + r*EMB_;
        #pragma unroll
        for (int j = 0; j < 4; j++) acc[j] += a * Pr[tid + j*128];
    }
    __nv_bfloat16* o = g_embB + (size_t)(t*B_ + b)*EMB_;
    #pragma unroll
    for (int j = 0; j < 4; j++) o[tid + j*128] = __float2bfloat16_rn(acc[j]);
}

// ---------------- init (after embed) -------------------------------------------
__global__ void init_kernel(const float* __restrict__ enc_state, float* out) {
    int i = blockIdx.x * blockDim.x + threadIdx.x;   // 32768
    if (i < B_*H_) {
        int b = i >> 10, j = i & 1023;
        float h0v = enc_state[i];
        float h1v = enc_state[B_*H_ + i];
        g_c0[i] = 0.f; g_c1[i] = 0.f; g_h1[i] = h1v;
        __nv_bfloat16 h0b = __float2bfloat16_rn(h0v);
        __nv_bfloat16 h1b = __float2bfloat16_rn(h1v);
        g_xb[0][b*K1_ + j]        = h0b;
        g_xb[0][b*K1_ + 1024 + j] = h1b;
        g_xa[0][b*K0_ + 1536 + j] = h0b;
        g_xa[0][b*K0_ + 512 + j]  = __float2bfloat16_rn(0.f);
        if (j < EMB_) g_xa[0][b*K0_ + j] = g_embB[b*EMB_ + j];
    }
    if (i < NRPAD) g_sumexp[i] = 0.f;
    if (i == 0) out[0] = 0.f;
}

// ---------------- fused gates GEMM + LSTM cell ---------------------------------
// grid 128 blocks (32 reordered cols = 8 units each), 128 threads, full-K accum
template<int WHICH>
__global__ void __launch_bounds__(128) fused_gates(int t, const float* __restrict__ bias) {
    constexpr int K   = WHICH ? K1_ : K0_;
    constexpr int NCH = K / 64;
    __shared__ __nv_bfloat16 xs[3][32][72];
    __shared__ __nv_bfloat16 ws[3][64][40];
    __shared__ float sg[32][33];
    int p = t & 1;
    const __nv_bfloat16* __restrict__ X = WHICH ? g_xb[p] : g_xa[p];
    const __nv_bfloat16* __restrict__ W = WHICH ? g_W1b : g_W0b;
    int tid = threadIdx.x, lane = tid & 31, w = tid >> 5;
    int cbase = blockIdx.x * 32;
    int wm = w >> 1, wn = w & 1;       // 16 rows x 16 cols per warp
    float acc[2][4] = {};

    auto load_chunk = [&](int ch) {
        int st = ch % 3; int kb = ch * 64;
        #pragma unroll
        for (int q = 0; q < 2; q++) {
            int idx = tid + q*128;
            int row = idx >> 3, kc = idx & 7;
            cp16(&xs[st][row][kc*8], X + row*K + kb + kc*8);
        }
        #pragma unroll
        for (int q = 0; q < 2; q++) {
            int idx = tid + q*128;
            int kr = idx >> 2, cc = idx & 3;
            cp16(&ws[st][kr][cc*8], W + (size_t)(kb + kr)*G4 + cbase + cc*8);
        }
    };
    load_chunk(0); cp_commit();
    load_chunk(1); cp_commit();
    for (int ch = 0; ch < NCH; ch++) {
        cp_wait1();
        __syncthreads();
        if (ch + 2 < NCH) load_chunk(ch + 2);
        cp_commit();
        int st = ch % 3;
        #pragma unroll
        for (int ks = 0; ks < 4; ks++) {
            uint32_t a[4], b[4];
            ldsm_x4  (a, &xs[st][wm*16 + (lane & 15)][ks*16 + (lane >> 4)*8]);
            ldsm_x4_t(b, &ws[st][ks*16 + (lane & 15)][wn*16 + (lane >> 4)*8]);
            mma_bf16(acc[0], a, b[0], b[1]);
            mma_bf16(acc[1], a, b[2], b[3]);
        }
    }
    // gates -> smem
    #pragma unroll
    for (int nt = 0; nt < 2; nt++) {
        int c = wn*16 + nt*8 + (lane & 3)*2;
        int r = wm*16 + (lane >> 2);
        sg[r][c]     = acc[nt][0];
        sg[r][c+1]   = acc[nt][1];
        sg[r+8][c]   = acc[nt][2];
        sg[r+8][c+1] = acc[nt][3];
    }
    __syncthreads();
    // cell: 32 rows x 8 units, 2 items per thread
    int ul = tid & 7, r0 = tid >> 3;             // r0 0..15
    int ug = blockIdx.x*8 + ul;
    float bi  = bias[ug];
    float bff = bias[1024 + ug];
    float bg  = bias[2048 + ug];
    float bo_ = bias[3072 + ug];
    float* Cst = WHICH ? g_c1 : g_c0;
    #pragma unroll
    for (int s = 0; s < 2; s++) {
        int r = r0 + s*16;
        float gi = sg[r][ul*4]     + bi;
        float gf = sg[r][ul*4 + 1] + bff;
        float gg = sg[r][ul*4 + 2] + bg;
        float go = sg[r][ul*4 + 3] + bo_;
        int ci = r*1024 + ug;
        float cn = sig_(gf)*Cst[ci] + sig_(gi)*tanhf(gg);
        float hn = sig_(go)*tanhf(cn);
        Cst[ci] = cn;
        __nv_bfloat16 hb = __float2bfloat16_rn(hn);
        if (WHICH == 0) {
            g_xb[p][r*K1_ + ug] = hb;                       // input to gates1 (this step)
            g_xa[1-p][r*K0_ + 1536 + ug] = hb;              // h0 for next step
        } else {
            g_xb[1-p][r*K1_ + 1024 + ug] = hb;              // h1 for next step
            g_h1[r*1024 + ug] = hn;                         // fp32 for attention
            g_featsB[(size_t)(t*B_ + r)*2048 + ug] = hb;    // feats h part
        }
    }
}

// ---------------- attention ------------------------------------------------------
__global__ void attn_kernel(int t, const float* __restrict__ enc,
                            const int* __restrict__ enc_lens) {
    int b = blockIdx.x;                  // 32 blocks, 256 threads
    __shared__ float hs[H_];
    __shared__ float sc[64];
    int tid = threadIdx.x;
    int p = t & 1;
    for (int i = tid; i < H_; i += 256) hs[i] = g_h1[b*H_ + i];
    __syncthreads();
    int w = tid >> 5, lane = tid & 31;
    int len = enc_lens[b];
    for (int s = w; s < S_; s += 8) {
        float a = 0.f;
        const float* e = enc + ((size_t)s*B_ + b)*C_;
        for (int cd = lane; cd < C_; cd += 32) a += e[cd]*hs[cd];
        #pragma unroll
        for (int o = 16; o; o >>= 1) a += __shfl_xor_sync(0xffffffffu, a, o);
        if (lane == 0) sc[s] = (s < len) ? a : -1.0e30f;
    }
    __syncthreads();
    if (w == 0) {
        float v0 = sc[lane];
        float v1 = (lane + 32 < S_) ? sc[lane + 32] : -1.0e30f;
        float m = fmaxf(v0, v1);
        #pragma unroll
        for (int o = 16; o; o >>= 1) m = fmaxf(m, __shfl_xor_sync(0xffffffffu, m, o));
        float e0 = __expf(v0 - m);
        float e1 = (lane + 32 < S_) ? __expf(v1 - m) : 0.f;
        float sum = e0 + e1;
        #pragma unroll
        for (int o = 16; o; o >>= 1) sum += __shfl_xor_sync(0xffffffffu, sum, o);
        sc[lane] = e0 / sum;
        if (lane + 32 < S_) sc[lane + 32] = e1 / sum;
    }
    __syncthreads();
    for (int cd = tid; cd < C_; cd += 256) {
        float a = 0.f;
        #pragma unroll 8
        for (int s = 0; s < S_; s++) a += sc[s]*enc[((size_t)s*B_ + b)*C_ + cd];
        __nv_bfloat16 ab = __float2bfloat16_rn(a);
        g_featsB[(size_t)(t*B_ + b)*2048 + 1024 + cd] = ab;  // feats ctx part
        g_xa[1-p][b*K0_ + 512 + cd] = ab;                    // ctx for next step
    }
    if (t + 1 < TM1) {   // stage next step's embedding
        const __nv_bfloat16* src = g_embB + ((size_t)(t+1)*B_ + b)*EMB_;
        for (int k = tid; k < EMB_; k += 256) g_xa[1-p][b*K0_ + k] = src[k];
    }
}

// ---------------- hproj = tanh(featsB @ WoB + bo) (bf16 mma, pipelined) -----------
__global__ void __launch_bounds__(256) hproj_mma(const float* __restrict__ bo) {
    __shared__ __nv_bfloat16 xs[3][32][72];
    __shared__ __nv_bfloat16 ws[3][64][72];
    int tid = threadIdx.x, lane = tid & 31, w = tid >> 5;   // 8 warps
    int cbase = blockIdx.x * 64;     // 8 tiles over 512
    int rbase = blockIdx.y * 32;     // 48 tiles over 1536
    int wm = w >> 2, wn = w & 3;     // 16 rows x 16 cols per warp
    float acc[2][4] = {};

    auto load_chunk = [&](int ch) {
        int st = ch % 3; int kb = ch * 64;
        {
            int row = tid >> 3, kc = tid & 7;
            cp16(&xs[st][row][kc*8], g_featsB + (size_t)(rbase + row)*2048 + kb + kc*8);
        }
        #pragma unroll
        for (int q = 0; q < 2; q++) {
            int idx = tid + q*256;
            int kr = idx >> 3, cc = idx & 7;
            cp16(&ws[st][kr][cc*8], g_WoB + (size_t)(kb + kr)*EMB_ + cbase + cc*8);
        }
    };
    load_chunk(0); cp_commit();
    load_chunk(1); cp_commit();
    for (int ch = 0; ch < 32; ch++) {
        cp_wait1();
        __syncthreads();
        if (ch + 2 < 32) load_chunk(ch + 2);
        cp_commit();
        int st = ch % 3;
        #pragma unroll
        for (int ks = 0; ks < 4; ks++) {
            uint32_t a[4], b[4];
            ldsm_x4  (a, &xs[st][wm*16 + (lane & 15)][ks*16 + (lane >> 4)*8]);
            ldsm_x4_t(b, &ws[st][ks*16 + (lane & 15)][wn*16 + (lane >> 4)*8]);
            mma_bf16(acc[0], a, b[0], b[1]);
            mma_bf16(acc[1], a, b[2], b[3]);
        }
    }
    #pragma unroll
    for (int nt = 0; nt < 2; nt++) {
        int col = cbase + wn*16 + nt*8 + (lane & 3)*2;
        float b0v = bo[col], b1v = bo[col+1];
        int r = rbase + wm*16 + (lane >> 2);
        if (r < NROWS) {
            g_hproj[(size_t)r*EMB_ + col]     = tanhf(acc[nt][0] + b0v);
            g_hproj[(size_t)r*EMB_ + col + 1] = tanhf(acc[nt][1] + b1v);
        }
        if (r + 8 < NROWS) {
            g_hproj[(size_t)(r+8)*EMB_ + col]     = tanhf(acc[nt][2] + b0v);
            g_hproj[(size_t)(r+8)*EMB_ + col + 1] = tanhf(acc[nt][3] + b1v);
        }
    }
}

// ---------------- tmp = hproj @ P^T ------------------------------------------------
__global__ void tmp_gemm(const float* __restrict__ P) {
    __shared__ float xs[32*33];
    __shared__ float ws[32*33];
    int tid = threadIdx.x, lane = tid & 31, rg = tid >> 5, r0 = rg*4;
    int cbase = blockIdx.x * 32;
    int rbase = blockIdx.y * 32;
    float a0=0.f, a1=0.f, a2=0.f, a3=0.f;
    for (int kb = 0; kb < 512; kb += 32) {
        #pragma unroll
        for (int i = 0; i < 4; i++) {
            int lin = tid + i*256;
            int kr = lin & 31, rr = lin >> 5;
            xs[kr*33 + rr] = g_hproj[(size_t)(rbase + rr)*EMB_ + kb + kr];
        }
        #pragma unroll
        for (int i = 0; i < 4; i++) {
            int lin = tid + i*256;
            int kr = lin & 31, j = lin >> 5;
            ws[kr*33 + j] = P[(size_t)(cbase + j)*EMB_ + kb + kr];
        }
        __syncthreads();
        #pragma unroll
        for (int kk = 0; kk < 32; kk++) {
            float bv = ws[kk*33 + lane];
            const float* xp = xs + kk*33 + r0;
            a0 += xp[0]*bv; a1 += xp[1]*bv; a2 += xp[2]*bv; a3 += xp[3]*bv;
        }
        __syncthreads();
    }
    int c = cbase + lane;
    g_tmp[(size_t)(rbase + r0 + 0)*RANK_ + c] = a0;
    g_tmp[(size_t)(rbase + r0 + 1)*RANK_ + c] = a1;
    g_tmp[(size_t)(rbase + r0 + 2)*RANK_ + c] = a2;
    g_tmp[(size_t)(rbase + r0 + 3)*RANK_ + c] = a3;
    g_tmpB[(size_t)(rbase + r0 + 0)*RANK_ + c] = __float2bfloat16_rn(a0);
    g_tmpB[(size_t)(rbase + r0 + 1)*RANK_ + c] = __float2bfloat16_rn(a1);
    g_tmpB[(size_t)(rbase + r0 + 2)*RANK_ + c] = __float2bfloat16_rn(a2);
    g_tmpB[(size_t)(rbase + r0 + 3)*RANK_ + c] = __float2bfloat16_rn(a3);
}

// ---------------- label logit (fp32) ------------------------------------------------
__global__ void label_kernel(const int* __restrict__ tok, const float* __restrict__ E) {
    int r = blockIdx.x*8 + (threadIdx.x >> 5);
    if (r >= NROWS) return;
    int lane = threadIdx.x & 31;
    int t = r / B_, b = r % B_;
    int lbl = tok[b*T_ + t + 1];
    float a = 0.f;
    for (int e = lane; e < RANK_; e += 32)
        a += g_tmp[(size_t)r*RANK_ + e] * E[(size_t)lbl*RANK_ + e];
    #pragma unroll
    for (int o = 16; o; o >>= 1) a += __shfl_xor_sync(0xffffffffu, a, o);
    if (lane == 0) g_lbl[r] = a;
}

// ---------------- sumexp via bf16 mma + poly exp ------------------------------------
__global__ void sumexp_mma() {
    __shared__ __nv_bfloat16 ts[64][136];
    __shared__ __nv_bfloat16 es[64][136];
    int tid = threadIdx.x, lane = tid & 31, w = tid >> 5;
    int vbase = blockIdx.x * 64, rbase = blockIdx.y * 64;
    #pragma unroll
    for (int q = 0; q < 8; q++) {
        int c = tid + q*128;
        int row = c >> 4, kc = c & 15;
        *(uint4*)&ts[row][kc*8] = *(const uint4*)&g_tmpB[(size_t)(rbase + row)*RANK_ + kc*8];
        *(uint4*)&es[row][kc*8] = *(const uint4*)&g_Eb[(size_t)(vbase + row)*RANK_ + kc*8];
    }
    __syncthreads();
    int m0 = (w & 1)*32, nb = (w >> 1)*32;
    float acc[2][4][4] = {};
    #pragma unroll
    for (int ks = 0; ks < 8; ks++) {
        uint32_t a0[4], a1[4], bA[4], bB[4];
        ldsm_x4(a0, &ts[m0 + (lane & 15)][ks*16 + (lane >> 4)*8]);
        ldsm_x4(a1, &ts[m0 + 16 + (lane & 15)][ks*16 + (lane >> 4)*8]);
        ldsm_x4(bA, &es[nb + (lane & 15)][ks*16 + (lane >> 4)*8]);
        ldsm_x4(bB, &es[nb + 16 + (lane & 15)][ks*16 + (lane >> 4)*8]);
        mma_bf16(acc[0][0], a0, bA[0], bA[2]);
        mma_bf16(acc[0][1], a0, bA[1], bA[3]);
        mma_bf16(acc[0][2], a0, bB[0], bB[2]);
        mma_bf16(acc[0][3], a0, bB[1], bB[3]);
        mma_bf16(acc[1][0], a1, bA[0], bA[2]);
        mma_bf16(acc[1][1], a1, bA[1], bA[3]);
        mma_bf16(acc[1][2], a1, bB[0], bB[2]);
        mma_bf16(acc[1][3], a1, bB[1], bB[3]);
    }
    #pragma unroll
    for (int mt = 0; mt < 2; mt++) {
        float sA = 0.f, sB = 0.f;
        #pragma unroll
        for (int nt = 0; nt < 4; nt++) {
            sA += fexp(acc[mt][nt][0]) + fexp(acc[mt][nt][1]);
            sB += fexp(acc[mt][nt][2]) + fexp(acc[mt][nt][3]);
        }
        sA += __shfl_xor_sync(0xffffffffu, sA, 1);
        sA += __shfl_xor_sync(0xffffffffu, sA, 2);
        sB += __shfl_xor_sync(0xffffffffu, sB, 1);
        sB += __shfl_xor_sync(0xffffffffu, sB, 2);
        if ((lane & 3) == 0) {
            int row = rbase + m0 + mt*16 + (lane >> 2);
            atomicAdd(&g_sumexp[row], sA);
            atomicAdd(&g_sumexp[row + 8], sB);
        }
    }
}

// ---------------- final loss ---------------------------------------------------------
__global__ void loss_kernel(const int* __restrict__ tgt_lens, float* out) {
    int r = blockIdx.x*blockDim.x + threadIdx.x;
    if (r >= NROWS) return;
    int t = r / B_, b = r % B_;
    if (t < tgt_lens[b] - 1) {
        float nll = logf(g_sumexp[r]) - g_lbl[r];
        atomicAdd(out, nll);
    }
}

// ---------------- launch ----------------------------------------------------------------
extern "C" void kernel_launch(void* const* d_in, const int* in_sizes, int n_in,
                              void* d_out, int out_size) {
    const float* encoded   = (const float*)d_in[0];
    const float* enc_state = (const float*)d_in[1];
    const int*   tok       = (const int*)  d_in[2];
    const int*   enc_lens  = (const int*)  d_in[3];
    const int*   tgt_lens  = (const int*)  d_in[4];
    const float* E         = (const float*)d_in[5];
    const float* P         = (const float*)d_in[6];
    const float* W0        = (const float*)d_in[7];
    const float* U0        = (const float*)d_in[8];
    const float* b0        = (const float*)d_in[9];
    const float* W1        = (const float*)d_in[10];
    const float* U1        = (const float*)d_in[11];
    const float* b1        = (const float*)d_in[12];
    const float* Wo        = (const float*)d_in[13];
    const float* bo        = (const float*)d_in[14];
    float* out = (float*)d_out;

    reorder_w<<<(K0_*1024 + K1_*1024 + 255)/256, 256>>>(W0, U0, W1, U1);
    convert_lin<<<((EE + WOE)/4 + 255)/256, 256>>>(E, Wo);
    embed_kernel<<<NROWS, 128>>>(E, P, tok);
    init_kernel<<<128, 256>>>(enc_state, out);

    for (int t = 0; t < TM1; t++) {
        fused_gates<0><<<128, 128>>>(t, b0);
        fused_gates<1><<<128, 128>>>(t, b1);
        attn_kernel<<<B_, 256>>>(t, encoded, enc_lens);
    }

    hproj_mma<<<dim3(8, 48), 256>>>(bo);
    tmp_gemm<<<dim3(4, 47), 256>>>(P);
    label_kernel<<<188, 256>>>(tok, E);
    sumexp_mma<<<dim3(500, 24), 128>>>();
    loss_kernel<<<6, 256>>>(tgt_lens, out);
}

// round 4
// speedup vs baseline: 1.1845x; 1.1845x over previous
#include <cuda_runtime.h>
#include <cuda_bf16.h>
#include <math.h>
#include <stdint.h>

#define S_     56
#define B_     32
#define C_     1024
#define T_     48
#define H_     1024
#define EMB_   512
#define RANK_  128
#define VOCAB_ 32000
#define TM1    47
#define NROWS  (TM1*B_)     /* 1504 */
#define NRPAD  1536
#define G4     (4*H_)       /* 4096 */
#define K0_    2560         /* EMB + C + H */
#define K1_    2048         /* 2H */

// ---------------- scratch (device globals) ----------------------------------
__device__ __align__(16) __nv_bfloat16 g_W0b[K0_*G4];
__device__ __align__(16) __nv_bfloat16 g_W1b[K1_*G4];
__device__ __align__(16) __nv_bfloat16 g_Eb[VOCAB_*RANK_];
__device__ __align__(16) __nv_bfloat16 g_WoB[2048*EMB_];
__device__ __align__(16) __nv_bfloat16 g_encB[S_*B_*C_];
__device__ __align__(16) __nv_bfloat16 g_embB[TM1*B_*EMB_];
__device__ __align__(16) __nv_bfloat16 g_xa[B_*K0_];      // [b][emb|ctx|h0]
__device__ __align__(16) __nv_bfloat16 g_xb[B_*K1_];      // [b][h0|h1]
__device__ __align__(16) __nv_bfloat16 g_featsB[NRPAD*2048];
__device__ __align__(16) __nv_bfloat16 g_tmpB[NRPAD*RANK_];
__device__ float g_gates_part[4][B_*G4];
__device__ float g_c0[B_*H_], g_c1[B_*H_];
__device__ float g_hproj[NROWS*EMB_];
__device__ float g_tmp[NROWS*RANK_];
__device__ float g_sumexp[NRPAD];
__device__ float g_lbl[NROWS];

// ---------------- helpers ------------------------------------------------
__device__ __forceinline__ void ldsm_x4(uint32_t* r, const void* p) {
    uint32_t a = (uint32_t)__cvta_generic_to_shared(p);
    asm volatile("ldmatrix.sync.aligned.m8n8.x4.shared.b16 {%0,%1,%2,%3}, [%4];"
        : "=r"(r[0]), "=r"(r[1]), "=r"(r[2]), "=r"(r[3]) : "r"(a));
}
__device__ __forceinline__ void ldsm_x4_t(uint32_t* r, const void* p) {
    uint32_t a = (uint32_t)__cvta_generic_to_shared(p);
    asm volatile("ldmatrix.sync.aligned.m8n8.x4.trans.shared.b16 {%0,%1,%2,%3}, [%4];"
        : "=r"(r[0]), "=r"(r[1]), "=r"(r[2]), "=r"(r[3]) : "r"(a));
}
__device__ __forceinline__ void mma_bf16(float* d, const uint32_t* a, uint32_t b0, uint32_t b1) {
    asm volatile("mma.sync.aligned.m16n8k16.row.col.f32.bf16.bf16.f32 "
        "{%0,%1,%2,%3},{%4,%5,%6,%7},{%8,%9},{%0,%1,%2,%3};"
        : "+f"(d[0]), "+f"(d[1]), "+f"(d[2]), "+f"(d[3])
        : "r"(a[0]), "r"(a[1]), "r"(a[2]), "r"(a[3]), "r"(b0), "r"(b1));
}
__device__ __forceinline__ void cp16(void* s, const void* g) {
    uint32_t sa = (uint32_t)__cvta_generic_to_shared(s);
    asm volatile("cp.async.cg.shared.global [%0], [%1], 16;" :: "r"(sa), "l"(g));
}
__device__ __forceinline__ void cp_commit() { asm volatile("cp.async.commit_group;"); }
__device__ __forceinline__ void cp_wait1()  { asm volatile("cp.async.wait_group 1;"); }

__device__ __forceinline__ float tanhfast(float x) {
    float r; asm("tanh.approx.f32 %0, %1;" : "=f"(r) : "f"(x)); return r;
}
__device__ __forceinline__ float sigf(float x) { return 0.5f*tanhfast(0.5f*x) + 0.5f; }

// fast exp via 2^y split; FMA-pipe
__device__ __forceinline__ float fexp(float x) {
    float y = x * 1.44269504088896341f;
    y = fminf(fmaxf(y, -120.f), 120.f);
    float n = rintf(y);
    float f = y - n;
    float p = 1.53386992e-4f;
    p = fmaf(p, f, 1.33938367e-3f);
    p = fmaf(p, f, 9.61843445e-3f);
    p = fmaf(p, f, 5.55041086e-2f);
    p = fmaf(p, f, 2.40226507e-1f);
    p = fmaf(p, f, 6.93147181e-1f);
    p = fmaf(p, f, 1.0f);
    int e = (int)n;
    return p * __int_as_float((e + 127) << 23);
}

// ---------------- fp32 -> bf16 conversion (all weights, enc) -------------------
#define W0E (K0_*G4)
#define W1E (K1_*G4)
#define EE  (VOCAB_*RANK_)
#define WOE (2048*EMB_)
#define ENCE (S_*B_*C_)
#define CVT_TOT (W0E + W1E + EE + WOE + ENCE)
__global__ void convert_all(const float* __restrict__ W0, const float* __restrict__ U0,
                            const float* __restrict__ W1, const float* __restrict__ U1,
                            const float* __restrict__ E, const float* __restrict__ Wo,
                            const float* __restrict__ enc) {
    long long i4 = ((long long)blockIdx.x*256 + threadIdx.x) * 4;
    if (i4 >= CVT_TOT) return;
    const float* src; __nv_bfloat16* dst;
    if (i4 < W0E) {
        long long o = i4;
        src = (o < (long long)1536*G4) ? (W0 + o) : (U0 + o - (long long)1536*G4);
        dst = g_W0b + o;
    } else if (i4 < W0E + W1E) {
        long long o = i4 - W0E;
        src = (o < (long long)1024*G4) ? (W1 + o) : (U1 + o - (long long)1024*G4);
        dst = g_W1b + o;
    } else if (i4 < W0E + W1E + EE) {
        long long o = i4 - W0E - W1E;
        src = E + o; dst = g_Eb + o;
    } else if (i4 < W0E + W1E + EE + WOE) {
        long long o = i4 - W0E - W1E - EE;
        src = Wo + o; dst = g_WoB + o;
    } else {
        long long o = i4 - W0E - W1E - EE - WOE;
        src = enc + o; dst = g_encB + o;
    }
    float4 v = *(const float4*)src;
    __nv_bfloat162* d2 = (__nv_bfloat162*)dst;
    d2[0] = __nv_bfloat162(__float2bfloat16_rn(v.x), __float2bfloat16_rn(v.y));
    d2[1] = __nv_bfloat162(__float2bfloat16_rn(v.z), __float2bfloat16_rn(v.w));
}

// ---------------- embedding: 8 rows x 512 cols per block ------------------------
__global__ void embed_kernel(const float* __restrict__ E, const float* __restrict__ P,
                             const int* __restrict__ tok) {
    __shared__ float er[8][128];
    int tid = threadIdx.x;                 // 256
    int rbase = blockIdx.x * 8;            // 188 blocks
    #pragma unroll
    for (int q = 0; q < 4; q++) {
        int idx = tid + q*256;
        int row = idx >> 7, k = idx & 127;
        int r = rbase + row;
        int t = r >> 5, b = r & 31;
        int token = tok[b*T_ + t];
        er[row][k] = E[(size_t)token*RANK_ + k];
    }
    __syncthreads();
    int c0 = tid, c1 = tid + 256;
    float acc[8][2] = {};
    for (int rr = 0; rr < 128; rr++) {
        float p0 = P[rr*EMB_ + c0];
        float p1 = P[rr*EMB_ + c1];
        #pragma unroll
        for (int row = 0; row < 8; row++) {
            float a = er[row][rr];
            acc[row][0] = fmaf(a, p0, acc[row][0]);
            acc[row][1] = fmaf(a, p1, acc[row][1]);
        }
    }
    #pragma unroll
    for (int row = 0; row < 8; row++) {
        __nv_bfloat16* o = g_embB + (size_t)(rbase + row)*EMB_;
        o[c0] = __float2bfloat16_rn(acc[row][0]);
        o[c1] = __float2bfloat16_rn(acc[row][1]);
    }
}

// ---------------- init (after embed) -------------------------------------------
__global__ void init_kernel(const float* __restrict__ enc_state, float* out) {
    int i = blockIdx.x * blockDim.x + threadIdx.x;   // 32768
    if (i < B_*H_) {
        int b = i >> 10, j = i & 1023;
        float h0v = enc_state[i];
        float h1v = enc_state[B_*H_ + i];
        g_c0[i] = 0.f; g_c1[i] = 0.f;
        __nv_bfloat16 h0b = __float2bfloat16_rn(h0v);
        __nv_bfloat16 h1b = __float2bfloat16_rn(h1v);
        g_xb[b*K1_ + j]        = h0b;
        g_xb[b*K1_ + 1024 + j] = h1b;
        g_xa[b*K0_ + 1536 + j] = h0b;
        g_xa[b*K0_ + 512 + j]  = __float2bfloat16_rn(0.f);
        if (j < EMB_) g_xa[b*K0_ + j] = g_embB[b*EMB_ + j];
    }
    if (i < NRPAD) g_sumexp[i] = 0.f;
    if (i == 0) out[0] = 0.f;
}

// ---------------- gates GEMM (bf16 mma, cp.async 3-stage, k-split 4) ------------
// out tile 32 x 64; grid (64 col-tiles, 4 k-splits); 128 threads
template<int WHICH>
__global__ void __launch_bounds__(128) gates_mma() {
    constexpr int K   = WHICH ? K1_ : K0_;
    constexpr int NCH = K / 256;            // chunks of 64 per k-split
    __shared__ __nv_bfloat16 xs[3][32][72];
    __shared__ __nv_bfloat16 ws[3][64][72];
    const __nv_bfloat16* __restrict__ X = WHICH ? g_xb : g_xa;
    const __nv_bfloat16* __restrict__ W = WHICH ? g_W1b : g_W0b;
    int tid = threadIdx.x, lane = tid & 31, w = tid >> 5;
    int cbase  = blockIdx.x * 64;
    int kstart = blockIdx.y * (K >> 2);
    int n0 = w * 16;
    float acc[2][2][4] = {};

    auto load_chunk = [&](int ch) {
        int st = ch % 3; int kb = kstart + ch*64;
        #pragma unroll
        for (int q = 0; q < 2; q++) {
            int c = tid*2 + q;
            int row = c >> 3, kc = c & 7;
            cp16(&xs[st][row][kc*8], X + row*K + kb + kc*8);
        }
        #pragma unroll
        for (int q = 0; q < 4; q++) {
            int c = tid + q*128;
            int row = c >> 3, cc = c & 7;
            cp16(&ws[st][row][cc*8], W + (size_t)(kb + row)*G4 + cbase + cc*8);
        }
    };
    load_chunk(0); cp_commit();
    load_chunk(1); cp_commit();
    for (int ch = 0; ch < NCH; ch++) {
        cp_wait1();
        __syncthreads();
        if (ch + 2 < NCH) load_chunk(ch + 2);
        cp_commit();
        int st = ch % 3;
        #pragma unroll
        for (int ks = 0; ks < 4; ks++) {
            uint32_t a0[4], a1[4], b[4];
            ldsm_x4(a0, &xs[st][(lane & 15)][ks*16 + (lane >> 4)*8]);
            ldsm_x4(a1, &xs[st][16 + (lane & 15)][ks*16 + (lane >> 4)*8]);
            ldsm_x4_t(b, &ws[st][ks*16 + (lane & 15)][n0 + (lane >> 4)*8]);
            mma_bf16(acc[0][0], a0, b[0], b[1]);
            mma_bf16(acc[0][1], a0, b[2], b[3]);
            mma_bf16(acc[1][0], a1, b[0], b[1]);
            mma_bf16(acc[1][1], a1, b[2], b[3]);
        }
        __syncthreads();
    }
    float* gp = g_gates_part[blockIdx.y];
    #pragma unroll
    for (int mt = 0; mt < 2; mt++)
        #pragma unroll
        for (int nt = 0; nt < 2; nt++) {
            int row = mt*16 + (lane >> 2);
            int col = cbase + n0 + nt*8 + 2*(lane & 3);
            *(float2*)&gp[(size_t)row*G4 + col]     = make_float2(acc[mt][nt][0], acc[mt][nt][1]);
            *(float2*)&gp[(size_t)(row+8)*G4 + col] = make_float2(acc[mt][nt][2], acc[mt][nt][3]);
        }
}

// ---------------- cell0: combine partials + LSTM, feed xa/xb --------------------
__global__ void cell0_kernel(const float* __restrict__ bias) {
    int b = blockIdx.x;                 // 32 blocks, 256 threads
    int tid = threadIdx.x;
    int j = tid * 4;
    size_t gb = (size_t)b*G4;
    float4 gi = *(const float4*)&bias[j];
    float4 gf = *(const float4*)&bias[j+1024];
    float4 gg = *(const float4*)&bias[j+2048];
    float4 go = *(const float4*)&bias[j+3072];
    #pragma unroll
    for (int p = 0; p < 4; p++) {
        const float* g = g_gates_part[p] + gb;
        float4 x;
        x = *(const float4*)&g[j];      gi.x+=x.x; gi.y+=x.y; gi.z+=x.z; gi.w+=x.w;
        x = *(const float4*)&g[j+1024]; gf.x+=x.x; gf.y+=x.y; gf.z+=x.z; gf.w+=x.w;
        x = *(const float4*)&g[j+2048]; gg.x+=x.x; gg.y+=x.y; gg.z+=x.z; gg.w+=x.w;
        x = *(const float4*)&g[j+3072]; go.x+=x.x; go.y+=x.y; go.z+=x.z; go.w+=x.w;
    }
    float4 cv = *(float4*)&g_c0[b*H_ + j];
    float cn0 = sigf(gf.x)*cv.x + sigf(gi.x)*tanhfast(gg.x);
    float cn1 = sigf(gf.y)*cv.y + sigf(gi.y)*tanhfast(gg.y);
    float cn2 = sigf(gf.z)*cv.z + sigf(gi.z)*tanhfast(gg.z);
    float cn3 = sigf(gf.w)*cv.w + sigf(gi.w)*tanhfast(gg.w);
    *(float4*)&g_c0[b*H_ + j] = make_float4(cn0, cn1, cn2, cn3);
    float h0 = sigf(go.x)*tanhfast(cn0);
    float h1 = sigf(go.y)*tanhfast(cn1);
    float h2 = sigf(go.z)*tanhfast(cn2);
    float h3 = sigf(go.w)*tanhfast(cn3);
    __nv_bfloat162 p01(__float2bfloat16_rn(h0), __float2bfloat16_rn(h1));
    __nv_bfloat162 p23(__float2bfloat16_rn(h2), __float2bfloat16_rn(h3));
    *(__nv_bfloat162*)&g_xb[b*K1_ + j]     = p01;      // gates1 input (this step)
    *(__nv_bfloat162*)&g_xb[b*K1_ + j + 2] = p23;
    *(__nv_bfloat162*)&g_xa[b*K0_ + 1536 + j]     = p01;  // h0 for next step
    *(__nv_bfloat162*)&g_xa[b*K0_ + 1536 + j + 2] = p23;
}

// ---------------- cell1 + attention fused ----------------------------------------
__global__ void cell1_attn(int t, const float* __restrict__ bias,
                           const int* __restrict__ enc_lens) {
    int b = blockIdx.x;                 // 32 blocks, 256 threads
    int tid = threadIdx.x;
    __shared__ float hs[H_];
    __shared__ float sc[64];
    // ---- cell1
    {
        int j = tid * 4;
        size_t gb = (size_t)b*G4;
        float4 gi = *(const float4*)&bias[j];
        float4 gf = *(const float4*)&bias[j+1024];
        float4 gg = *(const float4*)&bias[j+2048];
        float4 go = *(const float4*)&bias[j+3072];
        #pragma unroll
        for (int p = 0; p < 4; p++) {
            const float* g = g_gates_part[p] + gb;
            float4 x;
            x = *(const float4*)&g[j];      gi.x+=x.x; gi.y+=x.y; gi.z+=x.z; gi.w+=x.w;
            x = *(const float4*)&g[j+1024]; gf.x+=x.x; gf.y+=x.y; gf.z+=x.z; gf.w+=x.w;
            x = *(const float4*)&g[j+2048]; gg.x+=x.x; gg.y+=x.y; gg.z+=x.z; gg.w+=x.w;
            x = *(const float4*)&g[j+3072]; go.x+=x.x; go.y+=x.y; go.z+=x.z; go.w+=x.w;
        }
        float4 cv = *(float4*)&g_c1[b*H_ + j];
        float cn0 = sigf(gf.x)*cv.x + sigf(gi.x)*tanhfast(gg.x);
        float cn1 = sigf(gf.y)*cv.y + sigf(gi.y)*tanhfast(gg.y);
        float cn2 = sigf(gf.z)*cv.z + sigf(gi.z)*tanhfast(gg.z);
        float cn3 = sigf(gf.w)*cv.w + sigf(gi.w)*tanhfast(gg.w);
        *(float4*)&g_c1[b*H_ + j] = make_float4(cn0, cn1, cn2, cn3);
        float h0 = sigf(go.x)*tanhfast(cn0);
        float h1 = sigf(go.y)*tanhfast(cn1);
        float h2 = sigf(go.z)*tanhfast(cn2);
        float h3 = sigf(go.w)*tanhfast(cn3);
        hs[j] = h0; hs[j+1] = h1; hs[j+2] = h2; hs[j+3] = h3;
        __nv_bfloat162 p01(__float2bfloat16_rn(h0), __float2bfloat16_rn(h1));
        __nv_bfloat162 p23(__float2bfloat16_rn(h2), __float2bfloat16_rn(h3));
        *(__nv_bfloat162*)&g_xb[b*K1_ + 1024 + j]     = p01;  // h1 for next step
        *(__nv_bfloat162*)&g_xb[b*K1_ + 1024 + j + 2] = p23;
        __nv_bfloat16* fb = g_featsB + (size_t)(t*B_ + b)*2048;
        *(__nv_bfloat162*)&fb[j]     = p01;
        *(__nv_bfloat162*)&fb[j + 2] = p23;
    }
    __syncthreads();
    // ---- scores
    int w = tid >> 5, lane = tid & 31;
    int len = enc_lens[b];
    for (int s = w; s < S_; s += 8) {
        float a = 0.f;
        const __nv_bfloat16* e = g_encB + ((size_t)(s*B_ + b) << 10);
        #pragma unroll
        for (int q = 0; q < 4; q++) {
            int c = (lane + q*32) * 8;
            uint4 v = *(const uint4*)(e + c);
            const __nv_bfloat162* p2 = (const __nv_bfloat162*)&v;
            #pragma unroll
            for (int i = 0; i < 4; i++) {
                float2 f = __bfloat1622float2(p2[i]);
                a = fmaf(f.x, hs[c + 2*i], a);
                a = fmaf(f.y, hs[c + 2*i + 1], a);
            }
        }
        #pragma unroll
        for (int o = 16; o; o >>= 1) a += __shfl_xor_sync(0xffffffffu, a, o);
        if (lane == 0) sc[s] = (s < len) ? a : -1.0e30f;
    }
    __syncthreads();
    if (w == 0) {
        float v0 = sc[lane];
        float v1 = (lane + 32 < S_) ? sc[lane + 32] : -1.0e30f;
        float m = fmaxf(v0, v1);
        #pragma unroll
        for (int o = 16; o; o >>= 1) m = fmaxf(m, __shfl_xor_sync(0xffffffffu, m, o));
        float e0 = __expf(v0 - m);
        float e1 = (lane + 32 < S_) ? __expf(v1 - m) : 0.f;
        float sum = e0 + e1;
        #pragma unroll
        for (int o = 16; o; o >>= 1) sum += __shfl_xor_sync(0xffffffffu, sum, o);
        sc[lane] = e0 / sum;
        if (lane + 32 < S_) sc[lane + 32] = e1 / sum;
    }
    __syncthreads();
    // ---- context
    {
        int cd = tid * 4;
        float a0 = 0.f, a1 = 0.f, a2 = 0.f, a3 = 0.f;
        #pragma unroll 8
        for (int s = 0; s < S_; s++) {
            float wt = sc[s];
            uint2 v = *(const uint2*)(g_encB + ((size_t)(s*B_ + b) << 10) + cd);
            const __nv_bfloat162* p2 = (const __nv_bfloat162*)&v;
            float2 f0 = __bfloat1622float2(p2[0]);
            float2 f1 = __bfloat1622float2(p2[1]);
            a0 = fmaf(wt, f0.x, a0); a1 = fmaf(wt, f0.y, a1);
            a2 = fmaf(wt, f1.x, a2); a3 = fmaf(wt, f1.y, a3);
        }
        __nv_bfloat162 p01(__float2bfloat16_rn(a0), __float2bfloat16_rn(a1));
        __nv_bfloat162 p23(__float2bfloat16_rn(a2), __float2bfloat16_rn(a3));
        __nv_bfloat16* fb = g_featsB + (size_t)(t*B_ + b)*2048 + 1024;
        *(__nv_bfloat162*)&fb[cd]     = p01;
        *(__nv_bfloat162*)&fb[cd + 2] = p23;
        *(__nv_bfloat162*)&g_xa[b*K0_ + 512 + cd]     = p01;   // ctx for next step
        *(__nv_bfloat162*)&g_xa[b*K0_ + 512 + cd + 2] = p23;
    }
    // ---- stage next step's embedding
    if (t + 1 < TM1) {
        const __nv_bfloat16* src = g_embB + ((size_t)(t+1)*B_ + b)*EMB_;
        #pragma unroll
        for (int q = 0; q < 2; q++) {
            int k = tid + q*256;
            g_xa[b*K0_ + k] = src[k];
        }
    }
}

// ---------------- hproj = tanh(featsB @ WoB + bo) (bf16 mma, pipelined) -----------
__global__ void __launch_bounds__(256) hproj_mma(const float* __restrict__ bo) {
    __shared__ __nv_bfloat16 xs[3][32][72];
    __shared__ __nv_bfloat16 ws[3][64][72];
    int tid = threadIdx.x, lane = tid & 31, w = tid >> 5;   // 8 warps
    int cbase = blockIdx.x * 64;     // 8 tiles over 512
    int rbase = blockIdx.y * 32;     // 48 tiles over 1536
    int wm = w >> 2, wn = w & 3;
    float acc[2][4] = {};

    auto load_chunk = [&](int ch) {
        int st = ch % 3; int kb = ch * 64;
        {
            int row = tid >> 3, kc = tid & 7;
            cp16(&xs[st][row][kc*8], g_featsB + (size_t)(rbase + row)*2048 + kb + kc*8);
        }
        #pragma unroll
        for (int q = 0; q < 2; q++) {
            int idx = tid + q*256;
            int kr = idx >> 3, cc = idx & 7;
            cp16(&ws[st][kr][cc*8], g_WoB + (size_t)(kb + kr)*EMB_ + cbase + cc*8);
        }
    };
    load_chunk(0); cp_commit();
    load_chunk(1); cp_commit();
    for (int ch = 0; ch < 32; ch++) {
        cp_wait1();
        __syncthreads();
        if (ch + 2 < 32) load_chunk(ch + 2);
        cp_commit();
        int st = ch % 3;
        #pragma unroll
        for (int ks = 0; ks < 4; ks++) {
            uint32_t a[4], b[4];
            ldsm_x4  (a, &xs[st][wm*16 + (lane & 15)][ks*16 + (lane >> 4)*8]);
            ldsm_x4_t(b, &ws[st][ks*16 + (lane & 15)][wn*16 + (lane >> 4)*8]);
            mma_bf16(acc[0], a, b[0], b[1]);
            mma_bf16(acc[1], a, b[2], b[3]);
        }
        __syncthreads();
    }
    #pragma unroll
    for (int nt = 0; nt < 2; nt++) {
        int col = cbase + wn*16 + nt*8 + (lane & 3)*2;
        float b0v = bo[col], b1v = bo[col+1];
        int r = rbase + wm*16 + (lane >> 2);
        if (r < NROWS) {
            g_hproj[(size_t)r*EMB_ + col]     = tanhf(acc[nt][0] + b0v);
            g_hproj[(size_t)r*EMB_ + col + 1] = tanhf(acc[nt][1] + b1v);
        }
        if (r + 8 < NROWS) {
            g_hproj[(size_t)(r+8)*EMB_ + col]     = tanhf(acc[nt][2] + b0v);
            g_hproj[(size_t)(r+8)*EMB_ + col + 1] = tanhf(acc[nt][3] + b1v);
        }
    }
}

// ---------------- tmp = hproj @ P^T ------------------------------------------------
__global__ void tmp_gemm(const float* __restrict__ P) {
    __shared__ float xs[32*33];
    __shared__ float ws[32*33];
    int tid = threadIdx.x, lane = tid & 31, rg = tid >> 5, r0 = rg*4;
    int cbase = blockIdx.x * 32;
    int rbase = blockIdx.y * 32;
    float a0=0.f, a1=0.f, a2=0.f, a3=0.f;
    for (int kb = 0; kb < 512; kb += 32) {
        #pragma unroll
        for (int i = 0; i < 4; i++) {
            int lin = tid + i*256;
            int kr = lin & 31, rr = lin >> 5;
            xs[kr*33 + rr] = g_hproj[(size_t)(rbase + rr)*EMB_ + kb + kr];
        }
        #pragma unroll
        for (int i = 0; i < 4; i++) {
            int lin = tid + i*256;
            int kr = lin & 31, j = lin >> 5;
            ws[kr*33 + j] = P[(size_t)(cbase + j)*EMB_ + kb + kr];
        }
        __syncthreads();
        #pragma unroll
        for (int kk = 0; kk < 32; kk++) {
            float bv = ws[kk*33 + lane];
            const float* xp = xs + kk*33 + r0;
            a0 += xp[0]*bv; a1 += xp[1]*bv; a2 += xp[2]*bv; a3 += xp[3]*bv;
        }
        __syncthreads();
    }
    int c = cbase + lane;
    g_tmp[(size_t)(rbase + r0 + 0)*RANK_ + c] = a0;
    g_tmp[(size_t)(rbase + r0 + 1)*RANK_ + c] = a1;
    g_tmp[(size_t)(rbase + r0 + 2)*RANK_ + c] = a2;
    g_tmp[(size_t)(rbase + r0 + 3)*RANK_ + c] = a3;
    g_tmpB[(size_t)(rbase + r0 + 0)*RANK_ + c] = __float2bfloat16_rn(a0);
    g_tmpB[(size_t)(rbase + r0 + 1)*RANK_ + c] = __float2bfloat16_rn(a1);
    g_tmpB[(size_t)(rbase + r0 + 2)*RANK_ + c] = __float2bfloat16_rn(a2);
    g_tmpB[(size_t)(rbase + r0 + 3)*RANK_ + c] = __float2bfloat16_rn(a3);
}

// ---------------- label logit (fp32) ------------------------------------------------
__global__ void label_kernel(const int* __restrict__ tok, const float* __restrict__ E) {
    int r = blockIdx.x*8 + (threadIdx.x >> 5);
    if (r >= NROWS) return;
    int lane = threadIdx.x & 31;
    int t = r / B_, b = r % B_;
    int lbl = tok[b*T_ + t + 1];
    float a = 0.f;
    for (int e = lane; e < RANK_; e += 32)
        a += g_tmp[(size_t)r*RANK_ + e] * E[(size_t)lbl*RANK_ + e];
    #pragma unroll
    for (int o = 16; o; o >>= 1) a += __shfl_xor_sync(0xffffffffu, a, o);
    if (lane == 0) g_lbl[r] = a;
}

// ---------------- sumexp via bf16 mma + poly exp ------------------------------------
__global__ void sumexp_mma() {
    __shared__ __nv_bfloat16 ts[64][136];
    __shared__ __nv_bfloat16 es[64][136];
    int tid = threadIdx.x, lane = tid & 31, w = tid >> 5;
    int vbase = blockIdx.x * 64, rbase = blockIdx.y * 64;
    #pragma unroll
    for (int q = 0; q < 8; q++) {
        int c = tid + q*128;
        int row = c >> 4, kc = c & 15;
        *(uint4*)&ts[row][kc*8] = *(const uint4*)&g_tmpB[(size_t)(rbase + row)*RANK_ + kc*8];
        *(uint4*)&es[row][kc*8] = *(const uint4*)&g_Eb[(size_t)(vbase + row)*RANK_ + kc*8];
    }
    __syncthreads();
    int m0 = (w & 1)*32, nb = (w >> 1)*32;
    float acc[2][4][4] = {};
    #pragma unroll
    for (int ks = 0; ks < 8; ks++) {
        uint32_t a0[4], a1[4], bA[4], bB[4];
        ldsm_x4(a0, &ts[m0 + (lane & 15)][ks*16 + (lane >> 4)*8]);
        ldsm_x4(a1, &ts[m0 + 16 + (lane & 15)][ks*16 + (lane >> 4)*8]);
        ldsm_x4(bA, &es[nb + (lane & 15)][ks*16 + (lane >> 4)*8]);
        ldsm_x4(bB, &es[nb + 16 + (lane & 15)][ks*16 + (lane >> 4)*8]);
        mma_bf16(acc[0][0], a0, bA[0], bA[2]);
        mma_bf16(acc[0][1], a0, bA[1], bA[3]);
        mma_bf16(acc[0][2], a0, bB[0], bB[2]);
        mma_bf16(acc[0][3], a0, bB[1], bB[3]);
        mma_bf16(acc[1][0], a1, bA[0], bA[2]);
        mma_bf16(acc[1][1], a1, bA[1], bA[3]);
        mma_bf16(acc[1][2], a1, bB[0], bB[2]);
        mma_bf16(acc[1][3], a1, bB[1], bB[3]);
    }
    #pragma unroll
    for (int mt = 0; mt < 2; mt++) {
        float sA = 0.f, sB = 0.f;
        #pragma unroll
        for (int nt = 0; nt < 4; nt++) {
            sA += fexp(acc[mt][nt][0]) + fexp(acc[mt][nt][1]);
            sB += fexp(acc[mt][nt][2]) + fexp(acc[mt][nt][3]);
        }
        sA += __shfl_xor_sync(0xffffffffu, sA, 1);
        sA += __shfl_xor_sync(0xffffffffu, sA, 2);
        sB += __shfl_xor_sync(0xffffffffu, sB, 1);
        sB += __shfl_xor_sync(0xffffffffu, sB, 2);
        if ((lane & 3) == 0) {
            int row = rbase + m0 + mt*16 + (lane >> 2);
            atomicAdd(&g_sumexp[row], sA);
            atomicAdd(&g_sumexp[row + 8], sB);
        }
    }
}

// ---------------- final loss ---------------------------------------------------------
__global__ void loss_kernel(const int* __restrict__ tgt_lens, float* out) {
    int r = blockIdx.x*blockDim.x + threadIdx.x;
    if (r >= NROWS) return;
    int t = r / B_, b = r % B_;
    if (t < tgt_lens[b] - 1) {
        float nll = logf(g_sumexp[r]) - g_lbl[r];
        atomicAdd(out, nll);
    }
}

// ---------------- launch ----------------------------------------------------------------
extern "C" void kernel_launch(void* const* d_in, const int* in_sizes, int n_in,
                              void* d_out, int out_size) {
    const float* encoded   = (const float*)d_in[0];
    const float* enc_state = (const float*)d_in[1];
    const int*   tok       = (const int*)  d_in[2];
    const int*   enc_lens  = (const int*)  d_in[3];
    const int*   tgt_lens  = (const int*)  d_in[4];
    const float* E         = (const float*)d_in[5];
    const float* P         = (const float*)d_in[6];
    const float* W0        = (const float*)d_in[7];
    const float* U0        = (const float*)d_in[8];
    const float* b0        = (const float*)d_in[9];
    const float* W1        = (const float*)d_in[10];
    const float* U1        = (const float*)d_in[11];
    const float* b1        = (const float*)d_in[12];
    const float* Wo        = (const float*)d_in[13];
    const float* bo        = (const float*)d_in[14];
    float* out = (float*)d_out;

    convert_all<<<(CVT_TOT/4 + 255)/256, 256>>>(W0, U0, W1, U1, E, Wo, encoded);
    embed_kernel<<<NROWS/8, 256>>>(E, P, tok);
    init_kernel<<<128, 256>>>(enc_state, out);

    for (int t = 0; t < TM1; t++) {
        gates_mma<0><<<dim3(64, 4), 128>>>();
        cell0_kernel<<<B_, 256>>>(b0);
        gates_mma<1><<<dim3(64, 4), 128>>>();
        cell1_attn<<<B_, 256>>>(t, b1, enc_lens);
    }

    hproj_mma<<<dim3(8, 48), 256>>>(bo);
    tmp_gemm<<<dim3(4, 47), 256>>>(P);
    label_kernel<<<188, 256>>>(tok, E);
    sumexp_mma<<<dim3(500, 24), 128>>>();
    loss_kernel<<<6, 256>>>(tgt_lens, out);
}

// round 5
// speedup vs baseline: 1.5701x; 1.3255x over previous
#include <cuda_runtime.h>
#include <cuda_bf16.h>
#include <math.h>
#include <stdint.h>

#define S_     56
#define B_     32
#define C_     1024
#define T_     48
#define H_     1024
#define EMB_   512
#define RANK_  128
#define VOCAB_ 32000
#define TM1    47
#define NROWS  (TM1*B_)     /* 1504 */
#define NRPAD  1536
#define G4     (4*H_)       /* 4096 */
#define K0_    2560         /* EMB + C + H */
#define K1_    2048         /* 2H */
#define NBLK   256          /* persistent grid */

// ---------------- scratch (device globals) ----------------------------------
__device__ __align__(16) __nv_bfloat16 g_W0b[K0_*G4];
__device__ __align__(16) __nv_bfloat16 g_W1b[K1_*G4];
__device__ __align__(16) __nv_bfloat16 g_Eb[VOCAB_*RANK_];
__device__ __align__(16) __nv_bfloat16 g_WoB[2048*EMB_];
__device__ __align__(16) __nv_bfloat16 g_encB[S_*B_*C_];
__device__ __align__(16) __nv_bfloat16 g_embB[TM1*B_*EMB_];
__device__ __align__(16) __nv_bfloat16 g_xa[B_*K0_];      // [b][emb|ctx|h0]
__device__ __align__(16) __nv_bfloat16 g_xb[B_*K1_];      // [b][h0|h1]
__device__ __align__(16) __nv_bfloat16 g_featsB[NRPAD*2048];
__device__ __align__(16) __nv_bfloat16 g_tmpB[NRPAD*RANK_];
__device__ float g_gates_part[4][B_*G4];
__device__ float g_c0[B_*H_], g_c1[B_*H_];
__device__ float g_hproj[NROWS*EMB_];
__device__ float g_tmp[NROWS*RANK_];
__device__ float g_sumexp[NRPAD];
__device__ float g_lbl[NROWS];

// persistent-kernel barrier state
__device__ int g_bar_count = 0;
__device__ volatile int g_bar_gen = 0;

// ---------------- helpers ------------------------------------------------
__device__ __forceinline__ void ldsm_x4(uint32_t* r, const void* p) {
    uint32_t a = (uint32_t)__cvta_generic_to_shared(p);
    asm volatile("ldmatrix.sync.aligned.m8n8.x4.shared.b16 {%0,%1,%2,%3}, [%4];"
        : "=r"(r[0]), "=r"(r[1]), "=r"(r[2]), "=r"(r[3]) : "r"(a));
}
__device__ __forceinline__ void ldsm_x4_t(uint32_t* r, const void* p) {
    uint32_t a = (uint32_t)__cvta_generic_to_shared(p);
    asm volatile("ldmatrix.sync.aligned.m8n8.x4.trans.shared.b16 {%0,%1,%2,%3}, [%4];"
        : "=r"(r[0]), "=r"(r[1]), "=r"(r[2]), "=r"(r[3]) : "r"(a));
}
__device__ __forceinline__ void mma_bf16(float* d, const uint32_t* a, uint32_t b0, uint32_t b1) {
    asm volatile("mma.sync.aligned.m16n8k16.row.col.f32.bf16.bf16.f32 "
        "{%0,%1,%2,%3},{%4,%5,%6,%7},{%8,%9},{%0,%1,%2,%3};"
        : "+f"(d[0]), "+f"(d[1]), "+f"(d[2]), "+f"(d[3])
        : "r"(a[0]), "r"(a[1]), "r"(a[2]), "r"(a[3]), "r"(b0), "r"(b1));
}
__device__ __forceinline__ void cp16(void* s, const void* g) {
    uint32_t sa = (uint32_t)__cvta_generic_to_shared(s);
    asm volatile("cp.async.cg.shared.global [%0], [%1], 16;" :: "r"(sa), "l"(g));
}
__device__ __forceinline__ void cp_commit()  { asm volatile("cp.async.commit_group;"); }
__device__ __forceinline__ void cp_wait1()   { asm volatile("cp.async.wait_group 1;"); }
__device__ __forceinline__ void cp_waitall() { asm volatile("cp.async.wait_all;"); }

__device__ __forceinline__ float tanhfast(float x) {
    float r; asm("tanh.approx.f32 %0, %1;" : "=f"(r) : "f"(x)); return r;
}
__device__ __forceinline__ float sigf(float x) { return 0.5f*tanhfast(0.5f*x) + 0.5f; }

__device__ __forceinline__ float fexp(float x) {
    float y = x * 1.44269504088896341f;
    y = fminf(fmaxf(y, -120.f), 120.f);
    float n = rintf(y);
    float f = y - n;
    float p = 1.53386992e-4f;
    p = fmaf(p, f, 1.33938367e-3f);
    p = fmaf(p, f, 9.61843445e-3f);
    p = fmaf(p, f, 5.55041086e-2f);
    p = fmaf(p, f, 2.40226507e-1f);
    p = fmaf(p, f, 6.93147181e-1f);
    p = fmaf(p, f, 1.0f);
    int e = (int)n;
    return p * __int_as_float((e + 127) << 23);
}

// grid-wide barrier (all NBLK blocks co-resident)
__device__ __forceinline__ void gsync() {
    __syncthreads();
    if (threadIdx.x == 0) {
        __threadfence();
        int gen = g_bar_gen;
        if (atomicAdd(&g_bar_count, 1) == NBLK - 1) {
            g_bar_count = 0;
            __threadfence();
            g_bar_gen = gen + 1;
        } else {
            while (g_bar_gen == gen) __nanosleep(64);
        }
    }
    __syncthreads();
}

// ---------------- fp32 -> bf16 conversion -------------------------------------
#define W0E (K0_*G4)
#define W1E (K1_*G4)
#define EE  (VOCAB_*RANK_)
#define WOE (2048*EMB_)
#define ENCE (S_*B_*C_)
#define CVT_TOT (W0E + W1E + EE + WOE + ENCE)
__global__ void convert_all(const float* __restrict__ W0, const float* __restrict__ U0,
                            const float* __restrict__ W1, const float* __restrict__ U1,
                            const float* __restrict__ E, const float* __restrict__ Wo,
                            const float* __restrict__ enc) {
    long long i4 = ((long long)blockIdx.x*256 + threadIdx.x) * 4;
    if (i4 >= CVT_TOT) return;
    const float* src; __nv_bfloat16* dst;
    if (i4 < W0E) {
        long long o = i4;
        src = (o < (long long)1536*G4) ? (W0 + o) : (U0 + o - (long long)1536*G4);
        dst = g_W0b + o;
    } else if (i4 < W0E + W1E) {
        long long o = i4 - W0E;
        src = (o < (long long)1024*G4) ? (W1 + o) : (U1 + o - (long long)1024*G4);
        dst = g_W1b + o;
    } else if (i4 < W0E + W1E + EE) {
        long long o = i4 - W0E - W1E;
        src = E + o; dst = g_Eb + o;
    } else if (i4 < W0E + W1E + EE + WOE) {
        long long o = i4 - W0E - W1E - EE;
        src = Wo + o; dst = g_WoB + o;
    } else {
        long long o = i4 - W0E - W1E - EE - WOE;
        src = enc + o; dst = g_encB + o;
    }
    float4 v = *(const float4*)src;
    __nv_bfloat162* d2 = (__nv_bfloat162*)dst;
    d2[0] = __nv_bfloat162(__float2bfloat16_rn(v.x), __float2bfloat16_rn(v.y));
    d2[1] = __nv_bfloat162(__float2bfloat16_rn(v.z), __float2bfloat16_rn(v.w));
}

// ---------------- embedding ----------------------------------------------------
__global__ void embed_kernel(const float* __restrict__ E, const float* __restrict__ P,
                             const int* __restrict__ tok) {
    __shared__ float er[8][128];
    int tid = threadIdx.x;                 // 256
    int rbase = blockIdx.x * 8;            // 188 blocks
    #pragma unroll
    for (int q = 0; q < 4; q++) {
        int idx = tid + q*256;
        int row = idx >> 7, k = idx & 127;
        int r = rbase + row;
        int t = r >> 5, b = r & 31;
        int token = tok[b*T_ + t];
        er[row][k] = E[(size_t)token*RANK_ + k];
    }
    __syncthreads();
    int c0 = tid, c1 = tid + 256;
    float acc[8][2] = {};
    for (int rr = 0; rr < 128; rr++) {
        float p0 = P[rr*EMB_ + c0];
        float p1 = P[rr*EMB_ + c1];
        #pragma unroll
        for (int row = 0; row < 8; row++) {
            float a = er[row][rr];
            acc[row][0] = fmaf(a, p0, acc[row][0]);
            acc[row][1] = fmaf(a, p1, acc[row][1]);
        }
    }
    #pragma unroll
    for (int row = 0; row < 8; row++) {
        __nv_bfloat16* o = g_embB + (size_t)(rbase + row)*EMB_;
        o[c0] = __float2bfloat16_rn(acc[row][0]);
        o[c1] = __float2bfloat16_rn(acc[row][1]);
    }
}

// ---------------- init ----------------------------------------------------------
__global__ void init_kernel(const float* __restrict__ enc_state, float* out) {
    int i = blockIdx.x * blockDim.x + threadIdx.x;   // 32768
    if (i < B_*H_) {
        int b = i >> 10, j = i & 1023;
        float h0v = enc_state[i];
        float h1v = enc_state[B_*H_ + i];
        g_c0[i] = 0.f; g_c1[i] = 0.f;
        __nv_bfloat16 h0b = __float2bfloat16_rn(h0v);
        __nv_bfloat16 h1b = __float2bfloat16_rn(h1v);
        g_xb[b*K1_ + j]        = h0b;
        g_xb[b*K1_ + 1024 + j] = h1b;
        g_xa[b*K0_ + 1536 + j] = h0b;
        g_xa[b*K0_ + 512 + j]  = __float2bfloat16_rn(0.f);
        if (j < EMB_) g_xa[b*K0_ + j] = g_embB[b*EMB_ + j];
    }
    if (i < NRPAD) g_sumexp[i] = 0.f;
    if (i == 0) out[0] = 0.f;
}

// ================= persistent step loop ==========================================
#define XS_BYTES (3*32*72*2)
#define WS_BYTES (3*64*72*2)

template<int WHICH>
__device__ void gates_phase(char* sraw, int bid) {
    constexpr int K   = WHICH ? K1_ : K0_;
    constexpr int NCH = (K >> 2) / 64;
    typedef __nv_bfloat16 XsT[32][72];
    typedef __nv_bfloat16 WsT[64][72];
    XsT* xs = (XsT*)sraw;
    WsT* ws = (WsT*)(sraw + XS_BYTES);
    const __nv_bfloat16* __restrict__ X = WHICH ? g_xb : g_xa;
    const __nv_bfloat16* __restrict__ W = WHICH ? g_W1b : g_W0b;
    int tid = threadIdx.x, lane = tid & 31, w = tid >> 5;
    int cbase  = (bid & 63) * 64;
    int kstart = (bid >> 6) * (K >> 2);
    int n0 = w * 16;
    float acc[2][2][4] = {};

    auto load_chunk = [&](int ch) {
        int st = ch % 3; int kb = kstart + ch*64;
        #pragma unroll
        for (int q = 0; q < 2; q++) {
            int c = tid*2 + q;
            int row = c >> 3, kc = c & 7;
            cp16(&xs[st][row][kc*8], X + row*K + kb + kc*8);
        }
        #pragma unroll
        for (int q = 0; q < 4; q++) {
            int c = tid + q*128;
            int row = c >> 3, cc = c & 7;
            cp16(&ws[st][row][cc*8], W + (size_t)(kb + row)*G4 + cbase + cc*8);
        }
    };
    load_chunk(0); cp_commit();
    load_chunk(1); cp_commit();
    for (int ch = 0; ch < NCH; ch++) {
        cp_wait1();
        __syncthreads();
        if (ch + 2 < NCH) load_chunk(ch + 2);
        cp_commit();
        int st = ch % 3;
        #pragma unroll
        for (int ks = 0; ks < 4; ks++) {
            uint32_t a0[4], a1[4], b[4];
            ldsm_x4(a0, &xs[st][(lane & 15)][ks*16 + (lane >> 4)*8]);
            ldsm_x4(a1, &xs[st][16 + (lane & 15)][ks*16 + (lane >> 4)*8]);
            ldsm_x4_t(b, &ws[st][ks*16 + (lane & 15)][n0 + (lane >> 4)*8]);
            mma_bf16(acc[0][0], a0, b[0], b[1]);
            mma_bf16(acc[0][1], a0, b[2], b[3]);
            mma_bf16(acc[1][0], a1, b[0], b[1]);
            mma_bf16(acc[1][1], a1, b[2], b[3]);
        }
        __syncthreads();
    }
    cp_waitall();
    float* gp = g_gates_part[bid >> 6];
    #pragma unroll
    for (int mt = 0; mt < 2; mt++)
        #pragma unroll
        for (int nt = 0; nt < 2; nt++) {
            int row = mt*16 + (lane >> 2);
            int col = cbase + n0 + nt*8 + 2*(lane & 3);
            *(float2*)&gp[(size_t)row*G4 + col]     = make_float2(acc[mt][nt][0], acc[mt][nt][1]);
            *(float2*)&gp[(size_t)(row+8)*G4 + col] = make_float2(acc[mt][nt][2], acc[mt][nt][3]);
        }
}

__device__ __forceinline__ float4 ld_cg4(const float* p) {
    return __ldcg((const float4*)p);
}

__device__ void cell0_phase(int bid, const float* __restrict__ bias) {
    int b = bid >> 1;
    int j = (bid & 1)*512 + threadIdx.x*4;
    size_t gb = (size_t)b*G4;
    float4 gi = *(const float4*)&bias[j];
    float4 gf = *(const float4*)&bias[j+1024];
    float4 gg = *(const float4*)&bias[j+2048];
    float4 go = *(const float4*)&bias[j+3072];
    #pragma unroll
    for (int p = 0; p < 4; p++) {
        const float* g = g_gates_part[p] + gb;
        float4 x;
        x = ld_cg4(&g[j]);      gi.x+=x.x; gi.y+=x.y; gi.z+=x.z; gi.w+=x.w;
        x = ld_cg4(&g[j+1024]); gf.x+=x.x; gf.y+=x.y; gf.z+=x.z; gf.w+=x.w;
        x = ld_cg4(&g[j+2048]); gg.x+=x.x; gg.y+=x.y; gg.z+=x.z; gg.w+=x.w;
        x = ld_cg4(&g[j+3072]); go.x+=x.x; go.y+=x.y; go.z+=x.z; go.w+=x.w;
    }
    float4 cv = *(float4*)&g_c0[b*H_ + j];
    float cn0 = sigf(gf.x)*cv.x + sigf(gi.x)*tanhfast(gg.x);
    float cn1 = sigf(gf.y)*cv.y + sigf(gi.y)*tanhfast(gg.y);
    float cn2 = sigf(gf.z)*cv.z + sigf(gi.z)*tanhfast(gg.z);
    float cn3 = sigf(gf.w)*cv.w + sigf(gi.w)*tanhfast(gg.w);
    *(float4*)&g_c0[b*H_ + j] = make_float4(cn0, cn1, cn2, cn3);
    float h0 = sigf(go.x)*tanhfast(cn0);
    float h1 = sigf(go.y)*tanhfast(cn1);
    float h2 = sigf(go.z)*tanhfast(cn2);
    float h3 = sigf(go.w)*tanhfast(cn3);
    __nv_bfloat162 p01(__float2bfloat16_rn(h0), __float2bfloat16_rn(h1));
    __nv_bfloat162 p23(__float2bfloat16_rn(h2), __float2bfloat16_rn(h3));
    *(__nv_bfloat162*)&g_xb[b*K1_ + j]     = p01;
    *(__nv_bfloat162*)&g_xb[b*K1_ + j + 2] = p23;
    *(__nv_bfloat162*)&g_xa[b*K0_ + 1536 + j]     = p01;
    *(__nv_bfloat162*)&g_xa[b*K0_ + 1536 + j + 2] = p23;
}

__device__ void cell1_attn_phase(char* sraw, int b, int t,
                                 const float* __restrict__ bias,
                                 const int* __restrict__ enc_lens) {
    float* hs = (float*)sraw;            // 1024 floats
    float* sc = hs + 1024;               // 64 floats
    int tid = threadIdx.x;               // 128
    // ---- cell1: 8 units/thread
    #pragma unroll
    for (int half = 0; half < 2; half++) {
        int j = tid*8 + half*4;
        size_t gb = (size_t)b*G4;
        float4 gi = *(const float4*)&bias[j];
        float4 gf = *(const float4*)&bias[j+1024];
        float4 gg = *(const float4*)&bias[j+2048];
        float4 go = *(const float4*)&bias[j+3072];
        #pragma unroll
        for (int p = 0; p < 4; p++) {
            const float* g = g_gates_part[p] + gb;
            float4 x;
            x = ld_cg4(&g[j]);      gi.x+=x.x; gi.y+=x.y; gi.z+=x.z; gi.w+=x.w;
            x = ld_cg4(&g[j+1024]); gf.x+=x.x; gf.y+=x.y; gf.z+=x.z; gf.w+=x.w;
            x = ld_cg4(&g[j+2048]); gg.x+=x.x; gg.y+=x.y; gg.z+=x.z; gg.w+=x.w;
            x = ld_cg4(&g[j+3072]); go.x+=x.x; go.y+=x.y; go.z+=x.z; go.w+=x.w;
        }
        float4 cv = *(float4*)&g_c1[b*H_ + j];
        float cn0 = sigf(gf.x)*cv.x + sigf(gi.x)*tanhfast(gg.x);
        float cn1 = sigf(gf.y)*cv.y + sigf(gi.y)*tanhfast(gg.y);
        float cn2 = sigf(gf.z)*cv.z + sigf(gi.z)*tanhfast(gg.z);
        float cn3 = sigf(gf.w)*cv.w + sigf(gi.w)*tanhfast(gg.w);
        *(float4*)&g_c1[b*H_ + j] = make_float4(cn0, cn1, cn2, cn3);
        float h0 = sigf(go.x)*tanhfast(cn0);
        float h1 = sigf(go.y)*tanhfast(cn1);
        float h2 = sigf(go.z)*tanhfast(cn2);
        float h3 = sigf(go.w)*tanhfast(cn3);
        hs[j] = h0; hs[j+1] = h1; hs[j+2] = h2; hs[j+3] = h3;
        __nv_bfloat162 p01(__float2bfloat16_rn(h0), __float2bfloat16_rn(h1));
        __nv_bfloat162 p23(__float2bfloat16_rn(h2), __float2bfloat16_rn(h3));
        *(__nv_bfloat162*)&g_xb[b*K1_ + 1024 + j]     = p01;
        *(__nv_bfloat162*)&g_xb[b*K1_ + 1024 + j + 2] = p23;
        __nv_bfloat16* fb = g_featsB + (size_t)(t*B_ + b)*2048;
        *(__nv_bfloat162*)&fb[j]     = p01;
        *(__nv_bfloat162*)&fb[j + 2] = p23;
    }
    __syncthreads();
    // ---- scores
    int w = tid >> 5, lane = tid & 31;
    int len = enc_lens[b];
    for (int s = w; s < S_; s += 4) {
        float a = 0.f;
        const __nv_bfloat16* e = g_encB + ((size_t)(s*B_ + b) << 10);
        #pragma unroll
        for (int q = 0; q < 4; q++) {
            int c = (lane + q*32) * 8;
            uint4 v = *(const uint4*)(e + c);
            const __nv_bfloat162* p2 = (const __nv_bfloat162*)&v;
            #pragma unroll
            for (int i = 0; i < 4; i++) {
                float2 f = __bfloat1622float2(p2[i]);
                a = fmaf(f.x, hs[c + 2*i], a);
                a = fmaf(f.y, hs[c + 2*i + 1], a);
            }
        }
        #pragma unroll
        for (int o = 16; o; o >>= 1) a += __shfl_xor_sync(0xffffffffu, a, o);
        if (lane == 0) sc[s] = (s < len) ? a : -1.0e30f;
    }
    __syncthreads();
    if (w == 0) {
        float v0 = sc[lane];
        float v1 = (lane + 32 < S_) ? sc[lane + 32] : -1.0e30f;
        float m = fmaxf(v0, v1);
        #pragma unroll
        for (int o = 16; o; o >>= 1) m = fmaxf(m, __shfl_xor_sync(0xffffffffu, m, o));
        float e0 = __expf(v0 - m);
        float e1 = (lane + 32 < S_) ? __expf(v1 - m) : 0.f;
        float sum = e0 + e1;
        #pragma unroll
        for (int o = 16; o; o >>= 1) sum += __shfl_xor_sync(0xffffffffu, sum, o);
        sc[lane] = e0 / sum;
        if (lane + 32 < S_) sc[lane + 32] = e1 / sum;
    }
    __syncthreads();
    // ---- context: 8 cols/thread
    {
        int cd = tid * 8;
        float a[8] = {};
        #pragma unroll 8
        for (int s = 0; s < S_; s++) {
            float wt = sc[s];
            uint4 v = *(const uint4*)(g_encB + ((size_t)(s*B_ + b) << 10) + cd);
            const __nv_bfloat162* p2 = (const __nv_bfloat162*)&v;
            #pragma unroll
            for (int i = 0; i < 4; i++) {
                float2 f = __bfloat1622float2(p2[i]);
                a[2*i]   = fmaf(wt, f.x, a[2*i]);
                a[2*i+1] = fmaf(wt, f.y, a[2*i+1]);
            }
        }
        __nv_bfloat16* fb = g_featsB + (size_t)(t*B_ + b)*2048 + 1024;
        #pragma unroll
        for (int i = 0; i < 4; i++) {
            __nv_bfloat162 pp(__float2bfloat16_rn(a[2*i]), __float2bfloat16_rn(a[2*i+1]));
            *(__nv_bfloat162*)&fb[cd + 2*i] = pp;
            *(__nv_bfloat162*)&g_xa[b*K0_ + 512 + cd + 2*i] = pp;
        }
    }
    // ---- stage next step's embedding (4 per thread)
    if (t + 1 < TM1) {
        int k = tid * 4;
        *(uint2*)&g_xa[b*K0_ + k] =
            *(const uint2*)(g_embB + ((size_t)(t+1)*B_ + b)*EMB_ + k);
    }
}

__global__ void __launch_bounds__(128, 2) step_loop(const float* __restrict__ b0,
                                                    const float* __restrict__ b1,
                                                    const int* __restrict__ enc_lens) {
    __shared__ __align__(16) char sraw[XS_BYTES + WS_BYTES];
    int bid = blockIdx.x;
    for (int t = 0; t < TM1; t++) {
        gates_phase<0>(sraw, bid);
        gsync();
        if (bid < 64) cell0_phase(bid, b0);
        gsync();
        gates_phase<1>(sraw, bid);
        gsync();
        if (bid < 32) cell1_attn_phase(sraw, bid, t, b1, enc_lens);
        gsync();
    }
}

// ---------------- hproj = tanh(featsB @ WoB + bo) ---------------------------------
__global__ void __launch_bounds__(256) hproj_mma(const float* __restrict__ bo) {
    __shared__ __nv_bfloat16 xs[3][32][72];
    __shared__ __nv_bfloat16 ws[3][64][72];
    int tid = threadIdx.x, lane = tid & 31, w = tid >> 5;   // 8 warps
    int cbase = blockIdx.x * 64;
    int rbase = blockIdx.y * 32;
    int wm = w >> 2, wn = w & 3;
    float acc[2][4] = {};

    auto load_chunk = [&](int ch) {
        int st = ch % 3; int kb = ch * 64;
        {
            int row = tid >> 3, kc = tid & 7;
            cp16(&xs[st][row][kc*8], g_featsB + (size_t)(rbase + row)*2048 + kb + kc*8);
        }
        #pragma unroll
        for (int q = 0; q < 2; q++) {
            int idx = tid + q*256;
            int kr = idx >> 3, cc = idx & 7;
            cp16(&ws[st][kr][cc*8], g_WoB + (size_t)(kb + kr)*EMB_ + cbase + cc*8);
        }
    };
    load_chunk(0); cp_commit();
    load_chunk(1); cp_commit();
    for (int ch = 0; ch < 32; ch++) {
        cp_wait1();
        __syncthreads();
        if (ch + 2 < 32) load_chunk(ch + 2);
        cp_commit();
        int st = ch % 3;
        #pragma unroll
        for (int ks = 0; ks < 4; ks++) {
            uint32_t a[4], b[4];
            ldsm_x4  (a, &xs[st][wm*16 + (lane & 15)][ks*16 + (lane >> 4)*8]);
            ldsm_x4_t(b, &ws[st][ks*16 + (lane & 15)][wn*16 + (lane >> 4)*8]);
            mma_bf16(acc[0], a, b[0], b[1]);
            mma_bf16(acc[1], a, b[2], b[3]);
        }
        __syncthreads();
    }
    #pragma unroll
    for (int nt = 0; nt < 2; nt++) {
        int col = cbase + wn*16 + nt*8 + (lane & 3)*2;
        float b0v = bo[col], b1v = bo[col+1];
        int r = rbase + wm*16 + (lane >> 2);
        if (r < NROWS) {
            g_hproj[(size_t)r*EMB_ + col]     = tanhf(acc[nt][0] + b0v);
            g_hproj[(size_t)r*EMB_ + col + 1] = tanhf(acc[nt][1] + b1v);
        }
        if (r + 8 < NROWS) {
            g_hproj[(size_t)(r+8)*EMB_ + col]     = tanhf(acc[nt][2] + b0v);
            g_hproj[(size_t)(r+8)*EMB_ + col + 1] = tanhf(acc[nt][3] + b1v);
        }
    }
}

// ---------------- tmp = hproj @ P^T -------------------------------------------------
__global__ void tmp_gemm(const float* __restrict__ P) {
    __shared__ float xs[32*33];
    __shared__ float ws[32*33];
    int tid = threadIdx.x, lane = tid & 31, rg = tid >> 5, r0 = rg*4;
    int cbase = blockIdx.x * 32;
    int rbase = blockIdx.y * 32;
    float a0=0.f, a1=0.f, a2=0.f, a3=0.f;
    for (int kb = 0; kb < 512; kb += 32) {
        #pragma unroll
        for (int i = 0; i < 4; i++) {
            int lin = tid + i*256;
            int kr = lin & 31, rr = lin >> 5;
            xs[kr*33 + rr] = g_hproj[(size_t)(rbase + rr)*EMB_ + kb + kr];
        }
        #pragma unroll
        for (int i = 0; i < 4; i++) {
            int lin = tid + i*256;
            int kr = lin & 31, j = lin >> 5;
            ws[kr*33 + j] = P[(size_t)(cbase + j)*EMB_ + kb + kr];
        }
        __syncthreads();
        #pragma unroll
        for (int kk = 0; kk < 32; kk++) {
            float bv = ws[kk*33 + lane];
            const float* xp = xs + kk*33 + r0;
            a0 += xp[0]*bv; a1 += xp[1]*bv; a2 += xp[2]*bv; a3 += xp[3]*bv;
        }
        __syncthreads();
    }
    int c = cbase + lane;
    g_tmp[(size_t)(rbase + r0 + 0)*RANK_ + c] = a0;
    g_tmp[(size_t)(rbase + r0 + 1)*RANK_ + c] = a1;
    g_tmp[(size_t)(rbase + r0 + 2)*RANK_ + c] = a2;
    g_tmp[(size_t)(rbase + r0 + 3)*RANK_ + c] = a3;
    g_tmpB[(size_t)(rbase + r0 + 0)*RANK_ + c] = __float2bfloat16_rn(a0);
    g_tmpB[(size_t)(rbase + r0 + 1)*RANK_ + c] = __float2bfloat16_rn(a1);
    g_tmpB[(size_t)(rbase + r0 + 2)*RANK_ + c] = __float2bfloat16_rn(a2);
    g_tmpB[(size_t)(rbase + r0 + 3)*RANK_ + c] = __float2bfloat16_rn(a3);
}

// ---------------- label logit --------------------------------------------------------
__global__ void label_kernel(const int* __restrict__ tok, const float* __restrict__ E) {
    int r = blockIdx.x*8 + (threadIdx.x >> 5);
    if (r >= NROWS) return;
    int lane = threadIdx.x & 31;
    int t = r / B_, b = r % B_;
    int lbl = tok[b*T_ + t + 1];
    float a = 0.f;
    for (int e = lane; e < RANK_; e += 32)
        a += g_tmp[(size_t)r*RANK_ + e] * E[(size_t)lbl*RANK_ + e];
    #pragma unroll
    for (int o = 16; o; o >>= 1) a += __shfl_xor_sync(0xffffffffu, a, o);
    if (lane == 0) g_lbl[r] = a;
}

// ---------------- sumexp ---------------------------------------------------------------
__global__ void sumexp_mma() {
    __shared__ __nv_bfloat16 ts[64][136];
    __shared__ __nv_bfloat16 es[64][136];
    int tid = threadIdx.x, lane = tid & 31, w = tid >> 5;
    int vbase = blockIdx.x * 64, rbase = blockIdx.y * 64;
    #pragma unroll
    for (int q = 0; q < 8; q++) {
        int c = tid + q*128;
        int row = c >> 4, kc = c & 15;
        *(uint4*)&ts[row][kc*8] = *(const uint4*)&g_tmpB[(size_t)(rbase + row)*RANK_ + kc*8];
        *(uint4*)&es[row][kc*8] = *(const uint4*)&g_Eb[(size_t)(vbase + row)*RANK_ + kc*8];
    }
    __syncthreads();
    int m0 = (w & 1)*32, nb = (w >> 1)*32;
    float acc[2][4][4] = {};
    #pragma unroll
    for (int ks = 0; ks < 8; ks++) {
        uint32_t a0[4], a1[4], bA[4], bB[4];
        ldsm_x4(a0, &ts[m0 + (lane & 15)][ks*16 + (lane >> 4)*8]);
        ldsm_x4(a1, &ts[m0 + 16 + (lane & 15)][ks*16 + (lane >> 4)*8]);
        ldsm_x4(bA, &es[nb + (lane & 15)][ks*16 + (lane >> 4)*8]);
        ldsm_x4(bB, &es[nb + 16 + (lane & 15)][ks*16 + (lane >> 4)*8]);
        mma_bf16(acc[0][0], a0, bA[0], bA[2]);
        mma_bf16(acc[0][1], a0, bA[1], bA[3]);
        mma_bf16(acc[0][2], a0, bB[0], bB[2]);
        mma_bf16(acc[0][3], a0, bB[1], bB[3]);
        mma_bf16(acc[1][0], a1, bA[0], bA[2]);
        mma_bf16(acc[1][1], a1, bA[1], bA[3]);
        mma_bf16(acc[1][2], a1, bB[0], bB[2]);
        mma_bf16(acc[1][3], a1, bB[1], bB[3]);
    }
    #pragma unroll
    for (int mt = 0; mt < 2; mt++) {
        float sA = 0.f, sB = 0.f;
        #pragma unroll
        for (int nt = 0; nt < 4; nt++) {
            sA += fexp(acc[mt][nt][0]) + fexp(acc[mt][nt][1]);
            sB += fexp(acc[mt][nt][2]) + fexp(acc[mt][nt][3]);
        }
        sA += __shfl_xor_sync(0xffffffffu, sA, 1);
        sA += __shfl_xor_sync(0xffffffffu, sA, 2);
        sB += __shfl_xor_sync(0xffffffffu, sB, 1);
        sB += __shfl_xor_sync(0xffffffffu, sB, 2);
        if ((lane & 3) == 0) {
            int row = rbase + m0 + mt*16 + (lane >> 2);
            atomicAdd(&g_sumexp[row], sA);
            atomicAdd(&g_sumexp[row + 8], sB);
        }
    }
}

// ---------------- final loss ---------------------------------------------------------
__global__ void loss_kernel(const int* __restrict__ tgt_lens, float* out) {
    int r = blockIdx.x*blockDim.x + threadIdx.x;
    if (r >= NROWS) return;
    int t = r / B_, b = r % B_;
    if (t < tgt_lens[b] - 1) {
        float nll = logf(g_sumexp[r]) - g_lbl[r];
        atomicAdd(out, nll);
    }
}

// ---------------- launch ----------------------------------------------------------------
extern "C" void kernel_launch(void* const* d_in, const int* in_sizes, int n_in,
                              void* d_out, int out_size) {
    const float* encoded   = (const float*)d_in[0];
    const float* enc_state = (const float*)d_in[1];
    const int*   tok       = (const int*)  d_in[2];
    const int*   enc_lens  = (const int*)  d_in[3];
    const int*   tgt_lens  = (const int*)  d_in[4];
    const float* E         = (const float*)d_in[5];
    const float* P         = (const float*)d_in[6];
    const float* W0        = (const float*)d_in[7];
    const float* U0        = (const float*)d_in[8];
    const float* b0        = (const float*)d_in[9];
    const float* W1        = (const float*)d_in[10];
    const float* U1        = (const float*)d_in[11];
    const float* b1        = (const float*)d_in[12];
    const float* Wo        = (const float*)d_in[13];
    const float* bo        = (const float*)d_in[14];
    float* out = (float*)d_out;

    convert_all<<<(CVT_TOT/4 + 255)/256, 256>>>(W0, U0, W1, U1, E, Wo, encoded);
    embed_kernel<<<NROWS/8, 256>>>(E, P, tok);
    init_kernel<<<128, 256>>>(enc_state, out);

    step_loop<<<NBLK, 128>>>(b0, b1, enc_lens);

    hproj_mma<<<dim3(8, 48), 256>>>(bo);
    tmp_gemm<<<dim3(4, 47), 256>>>(P);
    label_kernel<<<188, 256>>>(tok, E);
    sumexp_mma<<<dim3(500, 24), 128>>>();
    loss_kernel<<<6, 256>>>(tgt_lens, out);
}